// round 16
// baseline (speedup 1.0000x reference)
#include <cuda_runtime.h>
#include <cuda_bf16.h>
#include <cstdint>

#define Bn    4096
#define TWOB  8192
#define D     256
#define BT    128               // tile edge
#define NT    (TWOB / BT)       // 64 tile bands
#define NTILES (NT * (NT + 1) / 2)   // 2080 triangular tiles
#define WPAD  3                 // band-start scheduling weight
#define WTOT  (NTILES + WPAD * NT)   // 2272

// sqrt(2 * log2(e)): inputs pre-scaled so acc = 2*log2e*sim -> exp2(acc) = exp(2*sim)
#define SCALE 1.6986436f

// Scratch (device globals — no allocation allowed)
__device__ __align__(16) uint8_t g_znq[TWOB * D];   // e4m3 of SCALE * normalized rows
__device__ float g_pos[Bn];      // exact fp32 positive cosine sims
__device__ float g_denom[TWOB];
__device__ unsigned int g_count;

// ---------------------------------------------------------------------------
__device__ __forceinline__ uint32_t smem_u32(const void* p) {
    uint32_t a;
    asm("{ .reg .u64 t; cvta.to.shared.u64 t, %1; cvt.u32.u64 %0, t; }" : "=r"(a) : "l"(p));
    return a;
}
__device__ __forceinline__ void ldsm_x4(uint32_t& r0, uint32_t& r1, uint32_t& r2, uint32_t& r3,
                                        uint32_t addr) {
    asm volatile("ldmatrix.sync.aligned.m8n8.x4.shared.b16 {%0,%1,%2,%3}, [%4];"
                 : "=r"(r0), "=r"(r1), "=r"(r2), "=r"(r3) : "r"(addr));
}
// FP8 e4m3 MMA with packed f16 accumulators: d0=(c0,c1) row q, d1=(c2,c3) row q+8
__device__ __forceinline__ void mma_fp8_h(uint32_t& d0, uint32_t& d1,
                                          const uint32_t* a, uint32_t b0, uint32_t b1) {
    asm volatile(
        "mma.sync.aligned.m16n8k32.row.col.f16.e4m3.e4m3.f16 "
        "{%0,%1}, {%2,%3,%4,%5}, {%6,%7}, {%0,%1};"
        : "+r"(d0), "+r"(d1)
        : "r"(a[0]), "r"(a[1]), "r"(a[2]), "r"(a[3]), "r"(b0), "r"(b1));
}
__device__ __forceinline__ uint16_t pack_e4m3(float v0, float v1) {
    uint16_t r;
    asm("cvt.rn.satfinite.e4m3x2.f32 %0, %1, %2;" : "=h"(r) : "f"(v1), "f"(v0));
    return r;
}
__device__ __forceinline__ uint32_t h2ex2(uint32_t x) {
    uint32_t r; asm("ex2.approx.f16x2 %0, %1;" : "=r"(r) : "r"(x)); return r;
}
__device__ __forceinline__ uint32_t hadd2(uint32_t a, uint32_t b) {
    uint32_t r; asm("add.f16x2 %0, %1, %2;" : "=r"(r) : "r"(a), "r"(b)); return r;
}
__device__ __forceinline__ void h2_floats(uint32_t v, float& lo, float& hi) {
    asm("{ .reg .b16 l, h; mov.b32 {l, h}, %2; cvt.f32.f16 %0, l; cvt.f32.f16 %1, h; }"
        : "=f"(lo), "=f"(hi) : "r"(v));
}
__device__ __forceinline__ float hsum(uint32_t v) {
    float lo, hi; h2_floats(v, lo, hi); return lo + hi;
}
__device__ __forceinline__ uint32_t dmask(int lc, int lr) {
    uint32_t m = 0xFFFFFFFFu;
    if (lc == lr)          m = 0xFFFF0000u;
    else if (lc + 1 == lr) m = 0x0000FFFFu;
    return m;
}
#define CP_COMMIT() asm volatile("cp.async.commit_group;" ::: "memory")
#define CP_WAIT0()  asm volatile("cp.async.wait_group 0;" ::: "memory")

// Async-stage one 128x256B fp8 tile. Row r (256 B = 16 chunks of 16 B);
// chunk c stored at r*256 + ((c ^ (r&7)) << 4).
__device__ __forceinline__ void stage_async(uint32_t sbase, const uint8_t* __restrict__ src,
                                            int row0, int tid) {
#pragma unroll
    for (int it = 0; it < 8; ++it) {
        int i = it * 256 + tid;
        int r = i >> 4, c = i & 15;
        const uint8_t* g = src + (size_t)(row0 + r) * 256 + c * 16;
        uint32_t dst = sbase + (uint32_t)r * 256u + (uint32_t)((c ^ (r & 7)) << 4);
        asm volatile("cp.async.cg.shared.global [%0], [%1], 16;" :: "r"(dst), "l"(g));
    }
}

__device__ __forceinline__ void decode_tile(int t, int& I, int& J) {
    int i = 0, s = 0;
    while (s + (NT - i) <= t) { s += NT - i; ++i; }
    I = i; J = i + (t - s);
}

// Weighted position -> tile index (each band start padded by WPAD positions,
// so CTAs that begin a band — and pay the synchronous A+B restage — own
// correspondingly fewer tiles).
__device__ __forceinline__ int wtile(int w) {
    int i = 0, s = 0;
    while (s + WPAD + (NT - i) <= w) { s += WPAD + (NT - i); ++i; }
    int j = w - s - WPAD; if (j < 0) j = 0;
    int cum = i * NT - (i * (i - 1)) / 2;
    return cum + j;
}

// ldmatrix address for 16-row x 32-byte (k32) fragment group.
__device__ __forceinline__ uint32_t frag_addr(uint32_t sbase, int m0, int kc, int lane) {
    int m  = lane >> 3;
    int r  = m0 + (lane & 7) + ((m & 1) << 3);
    int ch = 2 * kc + (m >> 1);
    return sbase + (uint32_t)r * 256u + (uint32_t)(((ch ^ (r & 7)) & 15) << 4);
}

// ---------------------------------------------------------------------------
// Kernel 1: normalize pairs; half-warp (16 lanes) per pair.
// Emits e4m3(SCALE * zn) rows i, i+Bn; exact fp32 positives; zeroes accums.
// ---------------------------------------------------------------------------
__global__ void k_prep(const float* __restrict__ z1, const float* __restrict__ z2) {
    int gtid = blockIdx.x * blockDim.x + threadIdx.x;
    if (gtid < TWOB) g_denom[gtid] = 0.f;
    if (gtid == 0)   g_count = 0u;
    int pair = gtid >> 4;
    int l16  = gtid & 15;
    if (pair >= Bn) return;
    const float4* a4 = (const float4*)(z1 + (size_t)pair * D);
    const float4* b4 = (const float4*)(z2 + (size_t)pair * D);
    float4 va[4], vb[4];
    float ss1 = 0.f, ss2 = 0.f, dot = 0.f;
#pragma unroll
    for (int j = 0; j < 4; j++) {
        va[j] = a4[l16 + 16 * j];
        vb[j] = b4[l16 + 16 * j];
        ss1 += va[j].x * va[j].x + va[j].y * va[j].y + va[j].z * va[j].z + va[j].w * va[j].w;
        ss2 += vb[j].x * vb[j].x + vb[j].y * vb[j].y + vb[j].z * vb[j].z + vb[j].w * vb[j].w;
        dot += va[j].x * vb[j].x + va[j].y * vb[j].y + va[j].z * vb[j].z + va[j].w * vb[j].w;
    }
#pragma unroll
    for (int o = 8; o > 0; o >>= 1) {
        ss1 += __shfl_xor_sync(0xffffffffu, ss1, o);
        ss2 += __shfl_xor_sync(0xffffffffu, ss2, o);
        dot += __shfl_xor_sync(0xffffffffu, dot, o);
    }
    float inv1 = 1.f / fmaxf(sqrtf(ss1), 1e-8f);
    float inv2 = 1.f / fmaxf(sqrtf(ss2), 1e-8f);
    float s1 = inv1 * SCALE, s2 = inv2 * SCALE;

    uint32_t* r1 = (uint32_t*)(g_znq + (size_t)pair * D);
    uint32_t* r2 = (uint32_t*)(g_znq + (size_t)(pair + Bn) * D);
#pragma unroll
    for (int j = 0; j < 4; j++) {
        uint32_t w1 = (uint32_t)pack_e4m3(va[j].x * s1, va[j].y * s1)
                    | ((uint32_t)pack_e4m3(va[j].z * s1, va[j].w * s1) << 16);
        uint32_t w2 = (uint32_t)pack_e4m3(vb[j].x * s2, vb[j].y * s2)
                    | ((uint32_t)pack_e4m3(vb[j].z * s2, vb[j].w * s2) << 16);
        r1[l16 + 16 * j] = w1;
        r2[l16 + 16 * j] = w2;
    }
    if (l16 == 0) g_pos[pair] = dot * inv1 * inv2;
}

// ---------------------------------------------------------------------------
// Kernel 2: symmetric e4m3 sim-GEMM (128x128 triangular tiles) with packed
// f16 accumulators; exp2 epilogue operates directly on the f16x2 accs.
// R10 structure exactly; single change: weighted tile scheduling so band-
// crossing CTAs get fewer tiles. 2 CTAs/SM; 8 warps (4 M x 2 N); warp tile
// 32x64; 8 k32 steps. Last-finishing CTA computes the final loss.
// ---------------------------------------------------------------------------
__global__ __launch_bounds__(256, 2) void k_sim_mma(float* __restrict__ out) {
    extern __shared__ char smem[];
    const uint32_t sbA  = smem_u32(smem);        // 32 KB
    const uint32_t sbB0 = sbA + 32768;           // 32 KB
    const uint32_t sbB1 = sbB0 + 32768;          // 32 KB
    float* sred  = (float*)(smem + 98304);       // 8 floats
    int*   sflag = (int*)(smem + 98304 + 64);

    const int t0 = wtile((int)(((long long)WTOT * blockIdx.x) / gridDim.x));
    const int t1 = wtile((int)(((long long)WTOT * (blockIdx.x + 1)) / gridDim.x));

    const int tid  = threadIdx.x;
    const int lane = tid & 31;
    const int wid  = tid >> 5;
    const int wm   = wid & 3;       // 4 warps along M (32 rows each)
    const int wn   = wid >> 2;      // 2 warps along N (64 cols each)
    const int qrow = lane >> 2;
    const int qcol = (lane & 3) * 2;

    int curI = -1;

    for (int t = t0; t < t1; ++t) {
        int I, J; decode_tile(t, I, J);
        const uint32_t sbB  = ((t - t0) & 1) ? sbB1 : sbB0;
        const uint32_t sbBn = ((t - t0) & 1) ? sbB0 : sbB1;

        if (I != curI) {
            stage_async(sbA, g_znq, I * BT, tid);
            stage_async(sbB, g_znq, J * BT, tid);
            CP_COMMIT(); CP_WAIT0();
            __syncthreads();
            curI = I;
        }
        if (t + 1 < t1) {
            int In, Jn; decode_tile(t + 1, In, Jn);
            if (In == curI) { stage_async(sbBn, g_znq, Jn * BT, tid); CP_COMMIT(); }
        }

        // ---- compute 128x128 tile: 8 k32 steps, f16x2 accumulators ----
        uint32_t acc[2][8][2];
#pragma unroll
        for (int mi = 0; mi < 2; mi++)
#pragma unroll
            for (int nj = 0; nj < 8; nj++) { acc[mi][nj][0] = 0u; acc[mi][nj][1] = 0u; }

#pragma unroll
        for (int kc = 0; kc < 8; ++kc) {
            uint32_t a[2][4];
#pragma unroll
            for (int mi = 0; mi < 2; mi++)
                ldsm_x4(a[mi][0], a[mi][1], a[mi][2], a[mi][3],
                        frag_addr(sbA, wm * 32 + mi * 16, kc, lane));
            uint32_t b[4][4];
#pragma unroll
            for (int nb = 0; nb < 4; nb++)
                ldsm_x4(b[nb][0], b[nb][1], b[nb][2], b[nb][3],
                        frag_addr(sbB, wn * 64 + nb * 16, kc, lane));
#pragma unroll
            for (int mi = 0; mi < 2; mi++)
#pragma unroll
                for (int nb = 0; nb < 4; nb++) {
                    mma_fp8_h(acc[mi][2 * nb + 0][0], acc[mi][2 * nb + 0][1],
                              a[mi], b[nb][0], b[nb][2]);
                    mma_fp8_h(acc[mi][2 * nb + 1][0], acc[mi][2 * nb + 1][1],
                              a[mi], b[nb][1], b[nb][3]);
                }
        }

        // ---- epilogue: exp2 directly on packed f16x2 accs ----
        const bool diag = (I == J);
        uint32_t rsA[2] = {0u, 0u};   // rows mi*16+qrow
        uint32_t rsB[2] = {0u, 0u};   // rows mi*16+qrow+8
        uint32_t csP[8];              // cols nj*8+qcol,+1
#pragma unroll
        for (int nj = 0; nj < 8; nj++) csP[nj] = 0u;

#pragma unroll
        for (int mi = 0; mi < 2; mi++) {
            const int lr0 = wm * 32 + mi * 16 + qrow;
            const int lr1 = lr0 + 8;
#pragma unroll
            for (int nj = 0; nj < 8; nj++) {
                const int lc = wn * 64 + nj * 8 + qcol;
                uint32_t e01 = h2ex2(acc[mi][nj][0]);
                uint32_t e23 = h2ex2(acc[mi][nj][1]);
                if (diag) {
                    e01 &= dmask(lc, lr0);
                    e23 &= dmask(lc, lr1);
                }
                rsA[mi] = hadd2(rsA[mi], e01);
                rsB[mi] = hadd2(rsB[mi], e23);
                csP[nj] = hadd2(csP[nj], hadd2(e01, e23));
            }
        }

        // row sums: packed reduce across the 4 qcol lanes, then horizontal
#pragma unroll
        for (int mi = 0; mi < 2; mi++) {
            rsA[mi] = hadd2(rsA[mi], __shfl_xor_sync(0xffffffffu, rsA[mi], 1));
            rsA[mi] = hadd2(rsA[mi], __shfl_xor_sync(0xffffffffu, rsA[mi], 2));
            rsB[mi] = hadd2(rsB[mi], __shfl_xor_sync(0xffffffffu, rsB[mi], 1));
            rsB[mi] = hadd2(rsB[mi], __shfl_xor_sync(0xffffffffu, rsB[mi], 2));
        }
        if ((lane & 3) == 0) {
            int rbase = I * BT + wm * 32 + qrow;
#pragma unroll
            for (int mi = 0; mi < 2; mi++) {
                atomicAdd(&g_denom[rbase + mi * 16],     hsum(rsA[mi]));
                atomicAdd(&g_denom[rbase + mi * 16 + 8], hsum(rsB[mi]));
            }
        }
        // col sums (symmetric contribution): packed reduce across qrow lanes
        if (!diag) {
#pragma unroll
            for (int nj = 0; nj < 8; nj++) {
                csP[nj] = hadd2(csP[nj], __shfl_xor_sync(0xffffffffu, csP[nj], 4));
                csP[nj] = hadd2(csP[nj], __shfl_xor_sync(0xffffffffu, csP[nj], 8));
                csP[nj] = hadd2(csP[nj], __shfl_xor_sync(0xffffffffu, csP[nj], 16));
            }
            if (lane < 4) {
                int cbase = J * BT + wn * 64 + lane * 2;
#pragma unroll
                for (int nj = 0; nj < 8; nj++) {
                    float lo, hi; h2_floats(csP[nj], lo, hi);
                    atomicAdd(&g_denom[cbase + nj * 8],     lo);
                    atomicAdd(&g_denom[cbase + nj * 8 + 1], hi);
                }
            }
        }

        CP_WAIT0();        // next B landed
        __syncthreads();
    }

    // ---- fused loss: last CTA to finish reduces 8192 logs ----
    __syncthreads();
    if (tid == 0) {
        __threadfence();
        unsigned int done = atomicAdd(&g_count, 1u);
        *sflag = (done == gridDim.x - 1);
    }
    __syncthreads();
    if (*sflag) {
        float l = 0.f;
#pragma unroll
        for (int r = 0; r < TWOB / 256; ++r) {
            int row = tid + 256 * r;
            l += __logf(g_denom[row]);
            if (row < Bn) l -= 2.f * __logf(g_pos[row]);
        }
#pragma unroll
        for (int o = 16; o > 0; o >>= 1) l += __shfl_xor_sync(0xffffffffu, l, o);
        if (lane == 0) sred[wid] = l;
        __syncthreads();
        if (tid == 0) {
            float tot = 0.f;
#pragma unroll
            for (int w = 0; w < 8; w++) tot += sred[w];
            out[0] = tot * (1.f / (float)TWOB);
        }
    }
}

// ---------------------------------------------------------------------------
extern "C" void kernel_launch(void* const* d_in, const int* in_sizes, int n_in,
                              void* d_out, int out_size) {
    const float* z1 = (const float*)d_in[0];
    const float* z2 = (const float*)d_in[1];
    float* out = (float*)d_out;

    int nsm = 148;
    cudaDeviceGetAttribute(&nsm, cudaDevAttrMultiProcessorCount, 0);

    const int smem_bytes = 3 * 32768 + 128;   // 98432 per CTA, 2 CTAs/SM
    cudaFuncSetAttribute(k_sim_mma, cudaFuncAttributeMaxDynamicSharedMemorySize, smem_bytes);

    k_prep<<<Bn * 16 / 256, 256>>>(z1, z2);
    k_sim_mma<<<2 * nsm, 256, smem_bytes>>>(out);
}

// round 17
// speedup vs baseline: 1.6651x; 1.6651x over previous
#include <cuda_runtime.h>
#include <cuda_bf16.h>
#include <cstdint>

#define Bn    4096
#define TWOB  8192
#define D     256
#define BT    128               // tile edge
#define NT    (TWOB / BT)       // 64 tile bands
#define NTILES (NT * (NT + 1) / 2)   // 2080 triangular tiles

// sqrt(2 * log2(e)): inputs pre-scaled so acc = 2*log2e*sim -> exp2(acc) = exp(2*sim)
#define SCALE 1.6986436f

// Scratch (device globals — no allocation allowed)
__device__ __align__(16) uint8_t g_znq[TWOB * D];   // e4m3 of SCALE * normalized rows
__device__ float g_pos[Bn];      // exact fp32 positive cosine sims
__device__ float g_denom[TWOB];
__device__ unsigned int g_count;

// ---------------------------------------------------------------------------
__device__ __forceinline__ uint32_t smem_u32(const void* p) {
    uint32_t a;
    asm("{ .reg .u64 t; cvta.to.shared.u64 t, %1; cvt.u32.u64 %0, t; }" : "=r"(a) : "l"(p));
    return a;
}
__device__ __forceinline__ void ldsm_x4(uint32_t& r0, uint32_t& r1, uint32_t& r2, uint32_t& r3,
                                        uint32_t addr) {
    asm volatile("ldmatrix.sync.aligned.m8n8.x4.shared.b16 {%0,%1,%2,%3}, [%4];"
                 : "=r"(r0), "=r"(r1), "=r"(r2), "=r"(r3) : "r"(addr));
}
// FP8 e4m3 MMA with packed f16 accumulators: d0=(c0,c1) row q, d1=(c2,c3) row q+8
__device__ __forceinline__ void mma_fp8_h(uint32_t& d0, uint32_t& d1,
                                          const uint32_t* a, uint32_t b0, uint32_t b1) {
    asm volatile(
        "mma.sync.aligned.m16n8k32.row.col.f16.e4m3.e4m3.f16 "
        "{%0,%1}, {%2,%3,%4,%5}, {%6,%7}, {%0,%1};"
        : "+r"(d0), "+r"(d1)
        : "r"(a[0]), "r"(a[1]), "r"(a[2]), "r"(a[3]), "r"(b0), "r"(b1));
}
__device__ __forceinline__ uint16_t pack_e4m3(float v0, float v1) {
    uint16_t r;
    asm("cvt.rn.satfinite.e4m3x2.f32 %0, %1, %2;" : "=h"(r) : "f"(v1), "f"(v0));
    return r;
}
__device__ __forceinline__ uint32_t h2ex2(uint32_t x) {
    uint32_t r; asm("ex2.approx.f16x2 %0, %1;" : "=r"(r) : "r"(x)); return r;
}
__device__ __forceinline__ uint32_t hadd2(uint32_t a, uint32_t b) {
    uint32_t r; asm("add.f16x2 %0, %1, %2;" : "=r"(r) : "r"(a), "r"(b)); return r;
}
__device__ __forceinline__ void h2_floats(uint32_t v, float& lo, float& hi) {
    asm("{ .reg .b16 l, h; mov.b32 {l, h}, %2; cvt.f32.f16 %0, l; cvt.f32.f16 %1, h; }"
        : "=f"(lo), "=f"(hi) : "r"(v));
}
__device__ __forceinline__ float hsum(uint32_t v) {
    float lo, hi; h2_floats(v, lo, hi); return lo + hi;
}
__device__ __forceinline__ uint32_t dmask(int lc, int lr) {
    uint32_t m = 0xFFFFFFFFu;
    if (lc == lr)          m = 0xFFFF0000u;
    else if (lc + 1 == lr) m = 0x0000FFFFu;
    return m;
}
#define CP_COMMIT() asm volatile("cp.async.commit_group;" ::: "memory")
#define CP_WAIT0()  asm volatile("cp.async.wait_group 0;" ::: "memory")

// Async-stage one 128x256B fp8 tile. Row r (256 B = 16 chunks of 16 B);
// chunk c stored at r*256 + ((c ^ (r&7)) << 4).
__device__ __forceinline__ void stage_async(uint32_t sbase, const uint8_t* __restrict__ src,
                                            int row0, int tid) {
#pragma unroll
    for (int it = 0; it < 8; ++it) {
        int i = it * 256 + tid;
        int r = i >> 4, c = i & 15;
        const uint8_t* g = src + (size_t)(row0 + r) * 256 + c * 16;
        uint32_t dst = sbase + (uint32_t)r * 256u + (uint32_t)((c ^ (r & 7)) << 4);
        asm volatile("cp.async.cg.shared.global [%0], [%1], 16;" :: "r"(dst), "l"(g));
    }
}

__device__ __forceinline__ void decode_tile(int t, int& I, int& J) {
    int i = 0, s = 0;
    while (s + (NT - i) <= t) { s += NT - i; ++i; }
    I = i; J = i + (t - s);
}

// ldmatrix address for 16-row x 32-byte (k32) fragment group.
__device__ __forceinline__ uint32_t frag_addr(uint32_t sbase, int m0, int kc, int lane) {
    int m  = lane >> 3;
    int r  = m0 + (lane & 7) + ((m & 1) << 3);
    int ch = 2 * kc + (m >> 1);
    return sbase + (uint32_t)r * 256u + (uint32_t)(((ch ^ (r & 7)) & 15) << 4);
}

// ---------------------------------------------------------------------------
// Kernel 1: normalize pairs; half-warp (16 lanes) per pair.
// Emits e4m3(SCALE * zn) rows i, i+Bn; exact fp32 positives; zeroes accums.
// ---------------------------------------------------------------------------
__global__ void k_prep(const float* __restrict__ z1, const float* __restrict__ z2) {
    int gtid = blockIdx.x * blockDim.x + threadIdx.x;
    if (gtid < TWOB) g_denom[gtid] = 0.f;
    if (gtid == 0)   g_count = 0u;
    int pair = gtid >> 4;
    int l16  = gtid & 15;
    if (pair >= Bn) return;
    const float4* a4 = (const float4*)(z1 + (size_t)pair * D);
    const float4* b4 = (const float4*)(z2 + (size_t)pair * D);
    float4 va[4], vb[4];
    float ss1 = 0.f, ss2 = 0.f, dot = 0.f;
#pragma unroll
    for (int j = 0; j < 4; j++) {
        va[j] = a4[l16 + 16 * j];
        vb[j] = b4[l16 + 16 * j];
        ss1 += va[j].x * va[j].x + va[j].y * va[j].y + va[j].z * va[j].z + va[j].w * va[j].w;
        ss2 += vb[j].x * vb[j].x + vb[j].y * vb[j].y + vb[j].z * vb[j].z + vb[j].w * vb[j].w;
        dot += va[j].x * vb[j].x + va[j].y * vb[j].y + va[j].z * vb[j].z + va[j].w * vb[j].w;
    }
#pragma unroll
    for (int o = 8; o > 0; o >>= 1) {
        ss1 += __shfl_xor_sync(0xffffffffu, ss1, o);
        ss2 += __shfl_xor_sync(0xffffffffu, ss2, o);
        dot += __shfl_xor_sync(0xffffffffu, dot, o);
    }
    float inv1 = 1.f / fmaxf(sqrtf(ss1), 1e-8f);
    float inv2 = 1.f / fmaxf(sqrtf(ss2), 1e-8f);
    float s1 = inv1 * SCALE, s2 = inv2 * SCALE;

    uint32_t* r1 = (uint32_t*)(g_znq + (size_t)pair * D);
    uint32_t* r2 = (uint32_t*)(g_znq + (size_t)(pair + Bn) * D);
#pragma unroll
    for (int j = 0; j < 4; j++) {
        uint32_t w1 = (uint32_t)pack_e4m3(va[j].x * s1, va[j].y * s1)
                    | ((uint32_t)pack_e4m3(va[j].z * s1, va[j].w * s1) << 16);
        uint32_t w2 = (uint32_t)pack_e4m3(vb[j].x * s2, vb[j].y * s2)
                    | ((uint32_t)pack_e4m3(vb[j].z * s2, vb[j].w * s2) << 16);
        r1[l16 + 16 * j] = w1;
        r2[l16 + 16 * j] = w2;
    }
    if (l16 == 0) g_pos[pair] = dot * inv1 * inv2;
}

// ---------------------------------------------------------------------------
// Kernel 2: symmetric e4m3 sim-GEMM (128x128 triangular tiles) with packed
// f16 accumulators; exp2 epilogue on the f16x2 accs. R10 structure verbatim
// (uniform tile split); single change: row sums deferred to band granularity
// (4 fp32 adds/tile; shuffles+atomics once per band). 2 CTAs/SM; 8 warps
// (4 M x 2 N); warp tile 32x64; 8 k32 steps. Last CTA computes the loss.
// ---------------------------------------------------------------------------
__global__ __launch_bounds__(256, 2) void k_sim_mma(float* __restrict__ out) {
    extern __shared__ char smem[];
    const uint32_t sbA  = smem_u32(smem);        // 32 KB
    const uint32_t sbB0 = sbA + 32768;           // 32 KB
    const uint32_t sbB1 = sbB0 + 32768;          // 32 KB
    float* sred  = (float*)(smem + 98304);       // 8 floats
    int*   sflag = (int*)(smem + 98304 + 64);

    const int t0 = (int)(((long long)NTILES * blockIdx.x) / gridDim.x);
    const int t1 = (int)(((long long)NTILES * (blockIdx.x + 1)) / gridDim.x);

    const int tid  = threadIdx.x;
    const int lane = tid & 31;
    const int wid  = tid >> 5;
    const int wm   = wid & 3;       // 4 warps along M (32 rows each)
    const int wn   = wid >> 2;      // 2 warps along N (64 cols each)
    const int qrow = lane >> 2;
    const int qcol = (lane & 3) * 2;

    int curI = -1;
    float rowacc[4] = {0.f, 0.f, 0.f, 0.f};   // deferred band row sums

    for (int t = t0; t < t1; ++t) {
        int I, J; decode_tile(t, I, J);
        const uint32_t sbB  = ((t - t0) & 1) ? sbB1 : sbB0;
        const uint32_t sbBn = ((t - t0) & 1) ? sbB0 : sbB1;

        if (I != curI) {
            // flush the previous band's deferred row sums
            if (curI >= 0) {
#pragma unroll
                for (int s = 0; s < 4; s++) {
                    rowacc[s] += __shfl_xor_sync(0xffffffffu, rowacc[s], 1);
                    rowacc[s] += __shfl_xor_sync(0xffffffffu, rowacc[s], 2);
                }
                if ((lane & 3) == 0) {
                    int rbase = curI * BT + wm * 32 + qrow;
                    atomicAdd(&g_denom[rbase],      rowacc[0]);
                    atomicAdd(&g_denom[rbase + 8],  rowacc[1]);
                    atomicAdd(&g_denom[rbase + 16], rowacc[2]);
                    atomicAdd(&g_denom[rbase + 24], rowacc[3]);
                }
#pragma unroll
                for (int s = 0; s < 4; s++) rowacc[s] = 0.f;
            }
            stage_async(sbA, g_znq, I * BT, tid);
            stage_async(sbB, g_znq, J * BT, tid);
            CP_COMMIT(); CP_WAIT0();
            __syncthreads();
            curI = I;
        }
        if (t + 1 < t1) {
            int In, Jn; decode_tile(t + 1, In, Jn);
            if (In == curI) { stage_async(sbBn, g_znq, Jn * BT, tid); CP_COMMIT(); }
        }

        // ---- compute 128x128 tile: 8 k32 steps, f16x2 accumulators ----
        uint32_t acc[2][8][2];
#pragma unroll
        for (int mi = 0; mi < 2; mi++)
#pragma unroll
            for (int nj = 0; nj < 8; nj++) { acc[mi][nj][0] = 0u; acc[mi][nj][1] = 0u; }

#pragma unroll
        for (int kc = 0; kc < 8; ++kc) {
            uint32_t a[2][4];
#pragma unroll
            for (int mi = 0; mi < 2; mi++)
                ldsm_x4(a[mi][0], a[mi][1], a[mi][2], a[mi][3],
                        frag_addr(sbA, wm * 32 + mi * 16, kc, lane));
            uint32_t b[4][4];
#pragma unroll
            for (int nb = 0; nb < 4; nb++)
                ldsm_x4(b[nb][0], b[nb][1], b[nb][2], b[nb][3],
                        frag_addr(sbB, wn * 64 + nb * 16, kc, lane));
#pragma unroll
            for (int mi = 0; mi < 2; mi++)
#pragma unroll
                for (int nb = 0; nb < 4; nb++) {
                    mma_fp8_h(acc[mi][2 * nb + 0][0], acc[mi][2 * nb + 0][1],
                              a[mi], b[nb][0], b[nb][2]);
                    mma_fp8_h(acc[mi][2 * nb + 1][0], acc[mi][2 * nb + 1][1],
                              a[mi], b[nb][1], b[nb][3]);
                }
        }

        // ---- epilogue: exp2 directly on packed f16x2 accs ----
        const bool diag = (I == J);
        uint32_t rsA[2] = {0u, 0u};   // rows mi*16+qrow
        uint32_t rsB[2] = {0u, 0u};   // rows mi*16+qrow+8
        uint32_t csP[8];              // cols nj*8+qcol,+1
#pragma unroll
        for (int nj = 0; nj < 8; nj++) csP[nj] = 0u;

#pragma unroll
        for (int mi = 0; mi < 2; mi++) {
            const int lr0 = wm * 32 + mi * 16 + qrow;
            const int lr1 = lr0 + 8;
#pragma unroll
            for (int nj = 0; nj < 8; nj++) {
                const int lc = wn * 64 + nj * 8 + qcol;
                uint32_t e01 = h2ex2(acc[mi][nj][0]);
                uint32_t e23 = h2ex2(acc[mi][nj][1]);
                if (diag) {
                    e01 &= dmask(lc, lr0);
                    e23 &= dmask(lc, lr1);
                }
                rsA[mi] = hadd2(rsA[mi], e01);
                rsB[mi] = hadd2(rsB[mi], e23);
                csP[nj] = hadd2(csP[nj], hadd2(e01, e23));
            }
        }
        // fold this tile's row partials into fp32 band accumulators (no shuffles)
        rowacc[0] += hsum(rsA[0]);
        rowacc[1] += hsum(rsB[0]);
        rowacc[2] += hsum(rsA[1]);
        rowacc[3] += hsum(rsB[1]);

        // col sums (symmetric contribution): packed reduce across qrow lanes
        if (!diag) {
#pragma unroll
            for (int nj = 0; nj < 8; nj++) {
                csP[nj] = hadd2(csP[nj], __shfl_xor_sync(0xffffffffu, csP[nj], 4));
                csP[nj] = hadd2(csP[nj], __shfl_xor_sync(0xffffffffu, csP[nj], 8));
                csP[nj] = hadd2(csP[nj], __shfl_xor_sync(0xffffffffu, csP[nj], 16));
            }
            if (lane < 4) {
                int cbase = J * BT + wn * 64 + lane * 2;
#pragma unroll
                for (int nj = 0; nj < 8; nj++) {
                    float lo, hi; h2_floats(csP[nj], lo, hi);
                    atomicAdd(&g_denom[cbase + nj * 8],     lo);
                    atomicAdd(&g_denom[cbase + nj * 8 + 1], hi);
                }
            }
        }

        CP_WAIT0();        // next B landed
        __syncthreads();
    }

    // flush the final band's deferred row sums
    if (curI >= 0) {
#pragma unroll
        for (int s = 0; s < 4; s++) {
            rowacc[s] += __shfl_xor_sync(0xffffffffu, rowacc[s], 1);
            rowacc[s] += __shfl_xor_sync(0xffffffffu, rowacc[s], 2);
        }
        if ((lane & 3) == 0) {
            int rbase = curI * BT + wm * 32 + qrow;
            atomicAdd(&g_denom[rbase],      rowacc[0]);
            atomicAdd(&g_denom[rbase + 8],  rowacc[1]);
            atomicAdd(&g_denom[rbase + 16], rowacc[2]);
            atomicAdd(&g_denom[rbase + 24], rowacc[3]);
        }
    }

    // ---- fused loss: last CTA to finish reduces 8192 logs ----
    __syncthreads();
    if (tid == 0) {
        __threadfence();
        unsigned int done = atomicAdd(&g_count, 1u);
        *sflag = (done == gridDim.x - 1);
    }
    __syncthreads();
    if (*sflag) {
        float l = 0.f;
#pragma unroll
        for (int r = 0; r < TWOB / 256; ++r) {
            int row = tid + 256 * r;
            l += __logf(g_denom[row]);
            if (row < Bn) l -= 2.f * __logf(g_pos[row]);
        }
#pragma unroll
        for (int o = 16; o > 0; o >>= 1) l += __shfl_xor_sync(0xffffffffu, l, o);
        if (lane == 0) sred[wid] = l;
        __syncthreads();
        if (tid == 0) {
            float tot = 0.f;
#pragma unroll
            for (int w = 0; w < 8; w++) tot += sred[w];
            out[0] = tot * (1.f / (float)TWOB);
        }
    }
}

// ---------------------------------------------------------------------------
extern "C" void kernel_launch(void* const* d_in, const int* in_sizes, int n_in,
                              void* d_out, int out_size) {
    const float* z1 = (const float*)d_in[0];
    const float* z2 = (const float*)d_in[1];
    float* out = (float*)d_out;

    int nsm = 148;
    cudaDeviceGetAttribute(&nsm, cudaDevAttrMultiProcessorCount, 0);

    const int smem_bytes = 3 * 32768 + 128;   // 98432 per CTA, 2 CTAs/SM
    cudaFuncSetAttribute(k_sim_mma, cudaFuncAttributeMaxDynamicSharedMemorySize, smem_bytes);

    k_prep<<<Bn * 16 / 256, 256>>>(z1, z2);
    k_sim_mma<<<2 * nsm, 256, smem_bytes>>>(out);
}